// round 14
// baseline (speedup 1.0000x reference)
#include <cuda_runtime.h>
#include <cstdint>

#define QS    2048.0f
#define IQS   (1.0f/2048.0f)
#define NEGQ  (-20000)
#define NEGF16 (-9.765625f)         // * 2048 = -20000 exactly
#define MAGIC 12582912.0f           // 1.5 * 2^23

// Problem constants
#define B    8
#define CIN  64
#define COUT 64
#define H    64
#define W    64
#define HW   (H*W)

// Quantized x: two planes in ONE array: [plane][B][CIN][66 rows][36 words]
#define XPH  66
#define XPWW 36
#define XPC  (XPH*XPWW)             // 2376
#define NPLANE ((size_t)B*CIN*XPC)  // plane stride (normal @0, shifted @NPLANE)

// Weights: [CIN][576]: words 0..511 = co*8+t (taps 0-7 dup), 512..575 = tap8[co]
#define WCIN 576

// Tiling: block = 2 rows x 64 px x 16 co, 128 thr = 2 cin-half groups of 64
#define TH   2
#define COB  16
#define COT  4
#define NC   4
#define CHALF 32
#define XS_C 272                    // 4 rows x 36 normal + 4 rows x 32 shifted
#define NXSW (NC*XS_C)              // 1088
#define WS_C 144                    // 128 tap words + 16 tap8 words
#define NWSW (NC*WS_C)              // 576
#define NITER (CHALF/NC)            // 8
#define REDS 20

__device__ __align__(16) unsigned xq_g[2*NPLANE];
__device__ __align__(16) unsigned wq_g[CIN*WCIN];

#define CP_ASYNC16(dst, src) \
    asm volatile("cp.async.cg.shared.global [%0], [%1], 16;\n" :: "r"(dst), "l"(src))
#define CP_COMMIT() asm volatile("cp.async.commit_group;\n" ::: "memory")
#define CP_WAIT0()  asm volatile("cp.async.wait_group 0;\n" ::: "memory")

__device__ __forceinline__ unsigned q16(float f) {     // bits; low16 = s16 round(f*QS)
    return __float_as_uint(fmaf(f, QS, MAGIC));
}
__device__ __forceinline__ unsigned packq(unsigned lo, unsigned hi) {
    return __byte_perm(lo, hi, 0x5410);
}

// ---- prep x: 2 units/thread, magic-FFMA quantize, both planes ----
#define XQB 594    // 594*512 = 304128 units = B*CIN*XPC/4

__global__ void prep_x(const float* __restrict__ x)
{
    int u0 = blockIdx.x * 512 + threadIdx.x;
    float4 fa[2], fm[2], fh[2];
    int qv[2];
#pragma unroll
    for (int k = 0; k < 2; ++k) {
        int q  = u0 + 256 * k;
        qv[k]  = q;
        int t  = q / 9;
        int sg = q - t * 9;
        int hh = t % XPH;
        int bc = t / XPH;
        const bool rowok = (hh >= 1 && hh <= H);
        const float* row = x + (size_t)bc * HW + (hh - 1) * W;
        const bool aok = rowok && (sg >= 1);
        const bool mok = rowok && (sg < 8);
        fa[k] = make_float4(NEGF16, NEGF16, NEGF16, NEGF16);
        fm[k] = fa[k];  fh[k] = fa[k];
        if (aok) fa[k] = *reinterpret_cast<const float4*>(row + sg * 8 - 4);
        if (mok) fm[k] = *reinterpret_cast<const float4*>(row + sg * 8);
        if (mok) fh[k] = *reinterpret_cast<const float4*>(row + sg * 8 + 4);
    }
#pragma unroll
    for (int k = 0; k < 2; ++k) {
        unsigned baw = q16(fa[k].w);
        unsigned bmx = q16(fm[k].x), bmy = q16(fm[k].y),
                 bmz = q16(fm[k].z), bmw = q16(fm[k].w);
        unsigned bhx = q16(fh[k].x), bhy = q16(fh[k].y),
                 bhz = q16(fh[k].z), bhw = q16(fh[k].w);
        uint4 nv, sv;
        nv.x = packq(baw, bmx);  nv.y = packq(bmy, bmz);
        nv.z = packq(bmw, bhx);  nv.w = packq(bhy, bhz);
        sv.x = packq(bmx, bmy);  sv.y = packq(bmz, bmw);
        sv.z = packq(bhx, bhy);  sv.w = packq(bhz, bhw);
        *reinterpret_cast<uint4*>(&xq_g[(size_t)qv[k] * 4])          = nv;
        *reinterpret_cast<uint4*>(&xq_g[NPLANE + (size_t)qv[k] * 4]) = sv;
    }
}

// ---- prep w: new layout [ci][co*8+t | 512+co] ----
#define WQB 144    // 144*256 = 36864 = CIN*WCIN

__global__ void prep_w(const float* __restrict__ wgt)
{
    int idx = blockIdx.x * blockDim.x + threadIdx.x;
    int ci  = idx / WCIN;
    int w   = idx - ci * WCIN;
    float v;
    if (w < 512) {
        int co = w >> 3, t = w & 7;
        v = wgt[(co * CIN + ci) * 9 + t];
    } else {
        int co = w - 512;
        v = wgt[(co * CIN + ci) * 9 + 8];
    }
    unsigned bits = q16(v);
    wq_g[idx] = __byte_perm(bits, bits, 0x1010);   // (s16, s16) dup
}

__device__ __forceinline__
void compute_chunk(const unsigned* __restrict__ xsb, const unsigned* __restrict__ wsb,
                   int c, int cog, int r, int j, unsigned (&A)[COT][4])
{
    unsigned tw[COT][9];
    const unsigned* wrow = wsb + c * WS_C + cog * (COT * 8);
    const unsigned* t8p  = wsb + c * WS_C + 128 + cog * COT;
#pragma unroll
    for (int u = 0; u < COT; ++u) {
        uint4 q0 = *reinterpret_cast<const uint4*>(wrow + u * 8);
        uint4 q1 = *reinterpret_cast<const uint4*>(wrow + u * 8 + 4);
        tw[u][0] = q0.x; tw[u][1] = q0.y; tw[u][2] = q0.z; tw[u][3] = q0.w;
        tw[u][4] = q1.x; tw[u][5] = q1.y; tw[u][6] = q1.z; tw[u][7] = q1.w;
        tw[u][8] = t8p[u];
    }
#pragma unroll
    for (int dr = 0; dr < 3; ++dr) {
        const unsigned* basen = xsb + c * XS_C + (r + dr) * 36 + 4 * j;
        const unsigned* bases = xsb + c * XS_C + 144 + (r + dr) * 32 + 4 * j;
        uint4 q  = *reinterpret_cast<const uint4*>(basen);
        unsigned w4 = basen[4];
        uint4 sq = *reinterpret_cast<const uint4*>(bases);
        unsigned Wv[5] = { q.x, q.y, q.z, q.w, w4 };
        unsigned S[4]  = { sq.x, sq.y, sq.z, sq.w };
#pragma unroll
        for (int u = 0; u < COT; ++u) {
            const unsigned t0 = tw[u][dr * 3 + 0];
            const unsigned t1 = tw[u][dr * 3 + 1];
            const unsigned t2 = tw[u][dr * 3 + 2];
#pragma unroll
            for (int p = 0; p < 4; ++p) {
                A[u][p] = __viaddmax_s16x2(Wv[p],     t0, A[u][p]);
                A[u][p] = __viaddmax_s16x2(S[p],      t1, A[u][p]);
                A[u][p] = __viaddmax_s16x2(Wv[p + 1], t2, A[u][p]);
            }
        }
    }
}

__global__ __launch_bounds__(128, 8)
void maxconv2d_kernel(float* __restrict__ out)
{
    __shared__ __align__(16) unsigned xs[4 * NXSW];   // 17408 B ([half][buf])
    __shared__ __align__(16) unsigned ws[4 * NWSW];   //  9216 B

    const int tid  = threadIdx.x;
    const int half = tid >> 6;
    const int gt   = tid & 63;

    const int b   = blockIdx.z >> 2;
    const int co0 = (blockIdx.z & 3) * COB;
    const int h0  = blockIdx.y * TH;

    const int cog = gt >> 4;
    const int sp  = gt & 15;
    const int r   = sp >> 3;
    const int j   = sp & 7;

    const unsigned NEG2 = ((unsigned)(NEGQ & 0xFFFF)) | ((unsigned)NEGQ << 16);
    unsigned A[COT][4];
#pragma unroll
    for (int u = 0; u < COT; ++u)
#pragma unroll
        for (int p = 0; p < 4; ++p) A[u][p] = NEG2;

    // ---- precompute flat staging slots ----
    size_t xsrc[5];                      // relative to xb (plane folded in)
#pragma unroll
    for (int m = 0; m < 5; ++m) {
        int wi  = 4 * (gt + 64 * m);
        int cin = wi / XS_C;
        int rem = wi - cin * XS_C;
        if (rem < 144) xsrc[m] = (size_t)cin * XPC + rem;
        else {
            int rr = (rem - 144) >> 5, cc = (rem - 144) & 31;
            xsrc[m] = (size_t)cin * XPC + rr * 36 + cc + NPLANE;
        }
    }
    int wsrc[3];
#pragma unroll
    for (int m = 0; m < 3; ++m) {
        int wi  = 4 * (gt + 64 * m);
        int cin = wi / WS_C;
        int rem = wi - cin * WS_C;
        wsrc[m] = cin * WCIN + ((rem < 128) ? (co0 * 8 + rem) : (512 + co0 + rem - 128));
    }

    const unsigned* xb = xq_g + (size_t)b * CIN * XPC + (size_t)half * CHALF * XPC
                       + (size_t)h0 * XPWW;
    const unsigned* wb = wq_g + half * CHALF * WCIN;

    const uint32_t xs_s = (uint32_t)__cvta_generic_to_shared(&xs[0]);
    const uint32_t ws_s = (uint32_t)__cvta_generic_to_shared(&ws[0]);

#define STAGE_X(xd, xp)                                                     \
    {                                                                       \
        _Pragma("unroll")                                                   \
        for (int m = 0; m < 5; ++m)                                         \
            if (m < 4 || gt < 16)                                           \
                CP_ASYNC16((xd) + (uint32_t)(16 * (gt + 64 * m)),           \
                           (xp) + xsrc[m]);                                 \
    }
#define STAGE_W(wd, wp)                                                     \
    {                                                                       \
        _Pragma("unroll")                                                   \
        for (int m = 0; m < 3; ++m)                                         \
            if (m < 2 || gt < 16)                                           \
                CP_ASYNC16((wd) + (uint32_t)(16 * (gt + 64 * m)),           \
                           (wp) + wsrc[m]);                                 \
    }

    // ---- stage 0 into (half, buf=0) ----
    {
        const uint32_t xd = xs_s + (uint32_t)((half * 2) * NXSW) * 4u;
        const uint32_t wd = ws_s + (uint32_t)((half * 2) * NWSW) * 4u;
        STAGE_X(xd, xb)
        STAGE_W(wd, wb)
        CP_COMMIT();
    }

    int buf = 0;
    for (int it = 0; it < NITER; ++it) {
        CP_WAIT0();
        __syncthreads();

        const bool more = (it + 1 < NITER);
        const unsigned* xc = xb + (it + 1) * NC * XPC;
        const unsigned* wc = wb + (it + 1) * NC * WCIN;
        const uint32_t xd = xs_s + (uint32_t)((half * 2 + (buf ^ 1)) * NXSW) * 4u;
        const uint32_t wd = ws_s + (uint32_t)((half * 2 + (buf ^ 1)) * NWSW) * 4u;

        const unsigned* xsb = xs + (half * 2 + buf) * NXSW;
        const unsigned* wsb = ws + (half * 2 + buf) * NWSW;

        compute_chunk(xsb, wsb, 0, cog, r, j, A);
        if (more) STAGE_X(xd, xc)
        compute_chunk(xsb, wsb, 1, cog, r, j, A);
        if (more) { STAGE_W(wd, wc) CP_COMMIT(); }
        compute_chunk(xsb, wsb, 2, cog, r, j, A);
        compute_chunk(xsb, wsb, 3, cog, r, j, A);

        buf ^= 1;
    }

    // ---- in-block combine (red aliased onto dead xs buffer) ----
    unsigned* red = xs;
    __syncthreads();
    if (half == 1) {
#pragma unroll
        for (int u = 0; u < COT; ++u) {
            uint4 st; st.x = A[u][0]; st.y = A[u][1]; st.z = A[u][2]; st.w = A[u][3];
            *reinterpret_cast<uint4*>(&red[gt * REDS + u * 4]) = st;
        }
    }
    __syncthreads();
    if (half == 0) {
#pragma unroll
        for (int u = 0; u < COT; ++u) {
            uint4 pr = *reinterpret_cast<const uint4*>(&red[gt * REDS + u * 4]);
            unsigned m0 = __vmaxs2(A[u][0], pr.x);
            unsigned m1 = __vmaxs2(A[u][1], pr.y);
            unsigned m2 = __vmaxs2(A[u][2], pr.z);
            unsigned m3 = __vmaxs2(A[u][3], pr.w);
            const int co = co0 + cog * COT + u;
            float* op = out + (((size_t)b * COUT + co) * H + (h0 + r)) * W + j * 8;
            float f[8];
            f[0] = ((int)(m0 << 16) >> 16) * IQS;  f[1] = ((int)m0 >> 16) * IQS;
            f[2] = ((int)(m1 << 16) >> 16) * IQS;  f[3] = ((int)m1 >> 16) * IQS;
            f[4] = ((int)(m2 << 16) >> 16) * IQS;  f[5] = ((int)m2 >> 16) * IQS;
            f[6] = ((int)(m3 << 16) >> 16) * IQS;  f[7] = ((int)m3 >> 16) * IQS;
            *reinterpret_cast<float4*>(op)     = make_float4(f[0], f[1], f[2], f[3]);
            *reinterpret_cast<float4*>(op + 4) = make_float4(f[4], f[5], f[6], f[7]);
        }
    }
#undef STAGE_X
#undef STAGE_W
}

extern "C" void kernel_launch(void* const* d_in, const int* in_sizes, int n_in,
                              void* d_out, int out_size)
{
    const float* x   = (const float*)d_in[0];
    const float* wgt = (const float*)d_in[1];
    float* out       = (float*)d_out;

    prep_x<<<XQB, 256>>>(x);
    prep_w<<<WQB, 256>>>(wgt);

    dim3 grid(1, H / TH, B * (COUT / COB));   // 1024 blocks
    maxconv2d_kernel<<<grid, 128>>>(out);
}

// round 15
// speedup vs baseline: 1.0900x; 1.0900x over previous
#include <cuda_runtime.h>
#include <cstdint>

#define QS    2048.0f
#define IQS   (1.0f/2048.0f)
#define NEGQ  (-20000)

// Problem constants
#define B    8
#define CIN  64
#define COUT 64
#define H    64
#define W    64
#define HW   (H*W)

// Padded quantized x: [B][CIN][66 rows][36 words] s16x2, two alignments
#define XPH  66
#define XPWW 36
#define XPC  (XPH*XPWW)   // 2376

// Dup weights: [CIN][COUT][12] words
#define WPC  12
#define WCIN (COUT*WPC)   // 768

// Tiling: block = 2 rows x 64 px x 16 co, 128 threads = 2 cin-half groups of 64
#define TH   2
#define COB  16
#define COT  4
#define NC   4
#define CHALF 32
#define XROWW 36
#define XS_C 288                    // 4 rows x 36 normal + 4 rows x 36 shifted
#define NXSW (NC*XS_C)              // 1152
#define WS_C (COB*WPC)              // 192
#define NWSW (NC*WS_C)              // 768
#define NITER (CHALF/NC)            // 8
#define REDS 20

__device__ __align__(16) unsigned xq_g [(size_t)B*CIN*XPC];   // normal: word k = cols(2k-1,2k)
__device__ __align__(16) unsigned xqs_g[(size_t)B*CIN*XPC];   // shifted: word k = cols(2k,2k+1)
__device__ __align__(16) unsigned wq_g [CIN*COUT*WPC];

#define CP_ASYNC16(dst, src) \
    asm volatile("cp.async.cg.shared.global [%0], [%1], 16;\n" :: "r"(dst), "l"(src))
#define CP_COMMIT() asm volatile("cp.async.commit_group;\n" ::: "memory")
#define CP_WAIT0()  asm volatile("cp.async.wait_group 0;\n" ::: "memory")

__device__ __forceinline__ unsigned pack16(int lo, int hi) {
    return (unsigned)(lo & 0xFFFF) | ((unsigned)hi << 16);
}

// ---- prep: one thread = one (quad, plane) unit; + weight tail blocks ----
// 2 * B*CIN*XPC/4 = 608256 x-units; 2376 x-blocks of 256; weights: 192 blocks
#define XQB 2376
#define WQB 192

__global__ void prep_all(const float* __restrict__ x, const float* __restrict__ wgt)
{
    if (blockIdx.x < XQB) {
        int u   = blockIdx.x * blockDim.x + threadIdx.x;
        int q   = u >> 1;                 // quad index
        int pl  = u & 1;                  // 0 = normal plane, 1 = shifted plane
        int t   = q / 9;
        int sg  = q - t * 9;
        int hh  = t % XPH;
        int bc  = t / XPH;
        const bool rowok = (hh >= 1 && hh <= H);
        const float* row = x + (size_t)bc * HW + (hh - 1) * W;
        const bool aok = rowok && (sg >= 1);
        const bool mok = rowok && (sg < 8);
        float4 fa = (pl == 0 && aok) ? *reinterpret_cast<const float4*>(row + sg * 8 - 4)
                                     : make_float4(0.f, 0.f, 0.f, 0.f);
        float4 fm = mok ? *reinterpret_cast<const float4*>(row + sg * 8)
                        : make_float4(0.f, 0.f, 0.f, 0.f);
        float4 fh = mok ? *reinterpret_cast<const float4*>(row + sg * 8 + 4)
                        : make_float4(0.f, 0.f, 0.f, 0.f);
        uint4 st;
        if (pl == 0) {
            // normal: word k = cols(2k-1,2k); quad covers cols sg*8-1 .. sg*8+6
            int v0 = aok ? __float2int_rn(fa.w * QS) : NEGQ;
            int v1 = mok ? __float2int_rn(fm.x * QS) : NEGQ;
            int v2 = mok ? __float2int_rn(fm.y * QS) : NEGQ;
            int v3 = mok ? __float2int_rn(fm.z * QS) : NEGQ;
            int v4 = mok ? __float2int_rn(fm.w * QS) : NEGQ;
            int v5 = mok ? __float2int_rn(fh.x * QS) : NEGQ;
            int v6 = mok ? __float2int_rn(fh.y * QS) : NEGQ;
            int v7 = mok ? __float2int_rn(fh.z * QS) : NEGQ;
            st.x = pack16(v0, v1);  st.y = pack16(v2, v3);
            st.z = pack16(v4, v5);  st.w = pack16(v6, v7);
            *reinterpret_cast<uint4*>(&xq_g[(size_t)q * 4]) = st;
        } else {
            // shifted: word k = cols(2k,2k+1); quad covers cols sg*8 .. sg*8+7
            int v0 = mok ? __float2int_rn(fm.x * QS) : NEGQ;
            int v1 = mok ? __float2int_rn(fm.y * QS) : NEGQ;
            int v2 = mok ? __float2int_rn(fm.z * QS) : NEGQ;
            int v3 = mok ? __float2int_rn(fm.w * QS) : NEGQ;
            int v4 = mok ? __float2int_rn(fh.x * QS) : NEGQ;
            int v5 = mok ? __float2int_rn(fh.y * QS) : NEGQ;
            int v6 = mok ? __float2int_rn(fh.z * QS) : NEGQ;
            int v7 = mok ? __float2int_rn(fh.w * QS) : NEGQ;
            st.x = pack16(v0, v1);  st.y = pack16(v2, v3);
            st.z = pack16(v4, v5);  st.w = pack16(v6, v7);
            *reinterpret_cast<uint4*>(&xqs_g[(size_t)q * 4]) = st;
        }
    } else {
        int idx = (blockIdx.x - XQB) * blockDim.x + threadIdx.x;
        int tp  = idx % WPC;
        int qd  = idx / WPC;
        int co  = qd % COUT;
        int ci  = qd / COUT;
        int val = (tp < 9) ? __float2int_rn(wgt[(co * CIN + ci) * 9 + tp] * QS) : 0;
        wq_g[idx] = pack16(val, val);
    }
}

__device__ __forceinline__
void compute_chunk(const unsigned* __restrict__ xsb, const unsigned* __restrict__ wsb,
                   int c, int cog, int r, int j, unsigned (&A)[COT][4])
{
    unsigned tw[COT][9];
    const unsigned* wrow = wsb + c * WS_C + cog * (COT * WPC);
#pragma unroll
    for (int u = 0; u < COT; ++u) {
        uint4 q0 = *reinterpret_cast<const uint4*>(wrow + u * WPC);
        uint4 q1 = *reinterpret_cast<const uint4*>(wrow + u * WPC + 4);
        tw[u][0] = q0.x; tw[u][1] = q0.y; tw[u][2] = q0.z; tw[u][3] = q0.w;
        tw[u][4] = q1.x; tw[u][5] = q1.y; tw[u][6] = q1.z; tw[u][7] = q1.w;
        tw[u][8] = wrow[u * WPC + 8];
    }
#pragma unroll
    for (int dr = 0; dr < 3; ++dr) {
        const unsigned* basen = xsb + c * XS_C + (r + dr) * XROWW + 4 * j;
        uint4 q  = *reinterpret_cast<const uint4*>(basen);
        unsigned w4 = basen[4];
        uint4 sq = *reinterpret_cast<const uint4*>(basen + 4 * XROWW);  // shifted copy
        unsigned Wv[5] = { q.x, q.y, q.z, q.w, w4 };
        unsigned S[4]  = { sq.x, sq.y, sq.z, sq.w };
#pragma unroll
        for (int u = 0; u < COT; ++u) {
            const unsigned t0 = tw[u][dr * 3 + 0];
            const unsigned t1 = tw[u][dr * 3 + 1];
            const unsigned t2 = tw[u][dr * 3 + 2];
#pragma unroll
            for (int p = 0; p < 4; ++p) {
                A[u][p] = __viaddmax_s16x2(Wv[p],     t0, A[u][p]);
                A[u][p] = __viaddmax_s16x2(S[p],      t1, A[u][p]);
                A[u][p] = __viaddmax_s16x2(Wv[p + 1], t2, A[u][p]);
            }
        }
    }
}

__global__ __launch_bounds__(128, 7)
void maxconv2d_kernel(float* __restrict__ out)
{
    __shared__ __align__(16) unsigned xs[4 * NXSW];   // 18432 B ([half][buf])
    __shared__ __align__(16) unsigned ws[4 * NWSW];   // 12288 B

    const int tid  = threadIdx.x;
    const int half = tid >> 6;
    const int gt   = tid & 63;

    const int b   = blockIdx.z >> 2;
    const int co0 = (blockIdx.z & 3) * COB;
    const int h0  = blockIdx.y * TH;

    const int cog = gt >> 4;
    const int sp  = gt & 15;
    const int r   = sp >> 3;
    const int j   = sp & 7;

    const int s  = gt & 15;
    const int cl = gt >> 4;

    const unsigned NEG2 = pack16(NEGQ, NEGQ);
    unsigned A[COT][4];
#pragma unroll
    for (int u = 0; u < COT; ++u)
#pragma unroll
        for (int p = 0; p < 4; ++p) A[u][p] = NEG2;

    const size_t xoffg = (size_t)b * CIN * XPC + (size_t)half * CHALF * XPC + h0 * XPWW;
    const unsigned* xb  = xq_g  + xoffg;
    const unsigned* xbs = xqs_g + xoffg;
    const unsigned* wb  = wq_g + (size_t)half * CHALF * WCIN + co0 * WPC;

    const uint32_t xs_s = (uint32_t)__cvta_generic_to_shared(&xs[0]);
    const uint32_t ws_s = (uint32_t)__cvta_generic_to_shared(&ws[0]);

#define STAGE_X(xd, xn, xsft)                                                        \
    {                                                                                \
        _Pragma("unroll")                                                            \
        for (int m = 0; m < 3; ++m)                                                  \
            if (m < 2 || s < 4) {                                                    \
                CP_ASYNC16((xd) + (uint32_t)(cl * XS_C + 4 * (s + 16 * m)) * 4u,     \
                           (xn) + cl * XPC + 4 * (s + 16 * m));                      \
                CP_ASYNC16((xd) + (uint32_t)(cl * XS_C + 144 + 4 * (s + 16 * m)) * 4u,\
                           (xsft) + cl * XPC + 4 * (s + 16 * m));                    \
            }                                                                        \
    }

    // ---- stage 0 into (half, buf=0) ----
    {
        const uint32_t xd = xs_s + (uint32_t)((half * 2) * NXSW) * 4u;
        const uint32_t wd = ws_s + (uint32_t)((half * 2) * NWSW) * 4u;
        STAGE_X(xd, xb, xbs)
#pragma unroll
        for (int m = 0; m < 3; ++m)
            CP_ASYNC16(wd + (uint32_t)(cl * WS_C + 4 * (s + 16 * m)) * 4u,
                       wb + cl * WCIN + 4 * (s + 16 * m));
        CP_COMMIT();
    }

    int buf = 0;
    for (int it = 0; it < NITER; ++it) {
        CP_WAIT0();
        __syncthreads();

        const bool more = (it + 1 < NITER);
        const unsigned* xc  = xb  + (it + 1) * NC * XPC;
        const unsigned* xcs = xbs + (it + 1) * NC * XPC;
        const unsigned* wc  = wb  + (it + 1) * NC * WCIN;
        const uint32_t xd = xs_s + (uint32_t)((half * 2 + (buf ^ 1)) * NXSW) * 4u;
        const uint32_t wd = ws_s + (uint32_t)((half * 2 + (buf ^ 1)) * NWSW) * 4u;

        const unsigned* xsb = xs + (half * 2 + buf) * NXSW;
        const unsigned* wsb = ws + (half * 2 + buf) * NWSW;

        compute_chunk(xsb, wsb, 0, cog, r, j, A);
        if (more) STAGE_X(xd, xc, xcs)
        compute_chunk(xsb, wsb, 1, cog, r, j, A);
        if (more) {
#pragma unroll
            for (int m = 0; m < 3; ++m)
                CP_ASYNC16(wd + (uint32_t)(cl * WS_C + 4 * (s + 16 * m)) * 4u,
                           wc + cl * WCIN + 4 * (s + 16 * m));
            CP_COMMIT();
        }
        compute_chunk(xsb, wsb, 2, cog, r, j, A);
        compute_chunk(xsb, wsb, 3, cog, r, j, A);

        buf ^= 1;
    }

    // ---- in-block combine (red aliased onto dead xs buffer) ----
    unsigned* red = xs;
    __syncthreads();   // all compute reads of xs done before overwrite
    if (half == 1) {
#pragma unroll
        for (int u = 0; u < COT; ++u) {
            uint4 st; st.x = A[u][0]; st.y = A[u][1]; st.z = A[u][2]; st.w = A[u][3];
            *reinterpret_cast<uint4*>(&red[gt * REDS + u * 4]) = st;
        }
    }
    __syncthreads();
    if (half == 0) {
#pragma unroll
        for (int u = 0; u < COT; ++u) {
            uint4 pr = *reinterpret_cast<const uint4*>(&red[gt * REDS + u * 4]);
            unsigned m0 = __vmaxs2(A[u][0], pr.x);
            unsigned m1 = __vmaxs2(A[u][1], pr.y);
            unsigned m2 = __vmaxs2(A[u][2], pr.z);
            unsigned m3 = __vmaxs2(A[u][3], pr.w);
            const int co = co0 + cog * COT + u;
            float* op = out + (((size_t)b * COUT + co) * H + (h0 + r)) * W + j * 8;
            float f[8];
            f[0] = ((int)(m0 << 16) >> 16) * IQS;  f[1] = ((int)m0 >> 16) * IQS;
            f[2] = ((int)(m1 << 16) >> 16) * IQS;  f[3] = ((int)m1 >> 16) * IQS;
            f[4] = ((int)(m2 << 16) >> 16) * IQS;  f[5] = ((int)m2 >> 16) * IQS;
            f[6] = ((int)(m3 << 16) >> 16) * IQS;  f[7] = ((int)m3 >> 16) * IQS;
            *reinterpret_cast<float4*>(op)     = make_float4(f[0], f[1], f[2], f[3]);
            *reinterpret_cast<float4*>(op + 4) = make_float4(f[4], f[5], f[6], f[7]);
        }
    }
#undef STAGE_X
}

extern "C" void kernel_launch(void* const* d_in, const int* in_sizes, int n_in,
                              void* d_out, int out_size)
{
    const float* x   = (const float*)d_in[0];
    const float* wgt = (const float*)d_in[1];
    float* out       = (float*)d_out;

    prep_all<<<XQB + WQB, 256>>>(x, wgt);

    dim3 grid(1, H / TH, B * (COUT / COB));   // 1024 blocks
    maxconv2d_kernel<<<grid, 128>>>(out);
}